// round 17
// baseline (speedup 1.0000x reference)
#include <cuda_runtime.h>
#include <math.h>

#define Bn 256
#define Tn 100
#define Fn 256
#define Hn 512
#define NB 128
#define NT 256
#define BT (Bn * Tn)
#define STW 12288                  // team-B stage words: A 4096 + B 8192
#define NSTG 3
#define EPIT 132
#define RESOFF 16384               // team-A resident weights offset (words)
#define SMEM_WORDS (NSTG * STW + 256)
#define SMEM_BYTES (SMEM_WORDS * 4)
#define BTF ((size_t)Bn * Tn * Fn)
#define NTH (NB * NT)

// ---------------- global scratch (allocation-free rule) ----------------
__device__ unsigned g_dtq[(size_t)400 * 4 * 4096];
__device__ unsigned g_gxmq[(size_t)400 * 8 * 4096];
__device__ unsigned g_mq[(size_t)4 * Tn * 4 * 4096];
__device__ unsigned g_Wtdhq[8 * 4 * 4096];
__device__ unsigned g_Wcombq[4 * 8 * 4096];
__device__ unsigned g_Whistq[16 * 8 * 1024];
__device__ unsigned g_Wfeatq[16 * 4 * 1024];
__device__ unsigned g_Wgq[32 * 16 * 4096];
__device__ unsigned g_hq[2 * 4 * 8 * 4096];
__device__ unsigned g_xcq[4 * 4 * 4096];
__device__ unsigned g_ccq[4 * 4 * 4096];
__device__ float g_gamma_h[(size_t)BT * Hn];
__device__ float g_alpha[(size_t)BT * Fn];
__device__ float g_bg[4 * Hn];
__device__ float g_cst[Bn * Hn];
__device__ float g_l1[Tn * 64], g_l2[Tn * 64], g_l3[Tn * 64], g_den[Tn * 64];
__device__ unsigned g_cnt, g_sense;
__device__ unsigned g_cnt_h[4], g_cnt_xh[4], g_cnt_cc[4];

__device__ __forceinline__ float sigmoidf_(float x) { return 1.0f / (1.0f + expf(-x)); }

__device__ __forceinline__ unsigned f2tf(float f) {
    unsigned u;
    asm("cvt.rna.tf32.f32 %0, %1;" : "=r"(u) : "f"(f));
    return u;
}

__device__ __forceinline__ int o_A(int r, int k) {
    return ((r >> 4) * 8 + (k >> 3)) * 128 + ((r & 7) * 4 + (k & 3)) * 4 +
           ((k & 4) >> 1) + ((r & 8) >> 3);
}

// vectorized init helpers (proven)
__device__ __forceinline__ void load8(const float* p, float* v) {
    float4 a = *(const float4*)p, b = *(const float4*)(p + 4);
    v[0] = a.x; v[1] = a.y; v[2] = a.z; v[3] = a.w;
    v[4] = b.x; v[5] = b.y; v[6] = b.z; v[7] = b.w;
}
__device__ __forceinline__ void storeA16(unsigned* tile, int rblk, int r0, int ko,
                                         const float* lo, const float* hi) {
    unsigned* dst = tile + (size_t)(rblk * 8 + ko) * 128 + r0 * 16;
#pragma unroll
    for (int tg = 0; tg < 4; tg++) {
        uint4 q = {f2tf(lo[tg]), f2tf(hi[tg]), f2tf(lo[tg + 4]), f2tf(hi[tg + 4])};
        *(uint4*)&dst[tg * 4] = q;
    }
}
__device__ __forceinline__ void storeB16(unsigned* tile, int nblk, int n0, int ko,
                                         const float* lo, const float* hi) {
    unsigned* dst = tile + (size_t)(nblk * 8 + ko) * 128 + n0 * 16;
#pragma unroll
    for (int tg = 0; tg < 4; tg++) {
        uint4 q = {f2tf(lo[tg]), f2tf(lo[tg + 4]), f2tf(hi[tg]), f2tf(hi[tg + 4])};
        *(uint4*)&dst[tg * 4] = q;
    }
}

#define MMA(d, A0, A1, A2, A3, B0, B1)                                          \
    asm volatile("mma.sync.aligned.m16n8k8.row.col.f32.tf32.tf32.f32 "          \
                 "{%0,%1,%2,%3},{%4,%5,%6,%7},{%8,%9},{%0,%1,%2,%3};"           \
                 : "+f"(d[0]), "+f"(d[1]), "+f"(d[2]), "+f"(d[3])               \
                 : "r"(A0), "r"(A1), "r"(A2), "r"(A3), "r"(B0), "r"(B1))

#define CPA(boff, p)                                                            \
    asm volatile("cp.async.cg.shared.global [%0], [%1], 16;"                    \
                 :: "r"(sbase + (unsigned)(boff)), "l"(p) : "memory")
#define CMT   asm volatile("cp.async.commit_group;" ::: "memory")
#define WAIT0 asm volatile("cp.async.wait_group 0;" ::: "memory")
#define WAIT1 asm volatile("cp.async.wait_group 1;" ::: "memory")
#define WAIT2 asm volatile("cp.async.wait_group 2;" ::: "memory")

#define LOADA(pA, s) do {                                                       \
    unsigned _off = (unsigned)((s) * STW * 4);                                  \
    _Pragma("unroll")                                                           \
    for (int _j = 0; _j < 4; _j++) { int _c = tid + _j * 256;                   \
        CPA(_off + (unsigned)_c * 16u, (pA) + _c * 4); }                        \
} while (0)
#define LOADB4K(pB, s) do {                                                     \
    unsigned _off = (unsigned)((s) * STW * 4) + 16384u;                         \
    _Pragma("unroll")                                                           \
    for (int _j = 0; _j < 4; _j++) { int _c = tid + _j * 256;                   \
        CPA(_off + (unsigned)_c * 16u, (pB) + _c * 4); }                        \
} while (0)
#define LOADBPC(pB0, pB1, s) do {                                               \
    unsigned _off = (unsigned)((s) * STW * 4) + 16384u;                         \
    _Pragma("unroll")                                                           \
    for (int _j = 0; _j < 4; _j++) { int _c = tid + _j * 256;                   \
        CPA(_off + (unsigned)_c * 16u, (pB0) + _c * 4);                         \
        CPA(_off + 16384u + (unsigned)_c * 16u, (pB1) + _c * 4); }              \
} while (0)
#define LOADA2(pA, s) do {                                                      \
    unsigned _off = (unsigned)((s) * 16384);                                    \
    _Pragma("unroll")                                                           \
    for (int _j = 0; _j < 4; _j++) { int _c = tid + _j * 256;                   \
        CPA(_off + (unsigned)_c * 16u, (pA) + _c * 4); }                        \
} while (0)

// ---------------- sync primitives (proven) ----------------
__device__ __forceinline__ void gsync(unsigned& sense) {
    __threadfence();
    __syncthreads();
    unsigned target = sense ^ 1u;
    if (threadIdx.x == 0) {
        unsigned old = atomicAdd(&g_cnt, 1u);
        if (old == NB - 1) {
            g_cnt = 0;
            __threadfence();
            atomicExch(&g_sense, target);
        } else {
            while (atomicAdd(&g_sense, 0u) != target) { __nanosleep(128); }
        }
        __threadfence();
    }
    sense = target;
    __syncthreads();
}
__device__ __forceinline__ void wait_ge(unsigned* cnt, unsigned target) {
    if (threadIdx.x == 0) {
        while (atomicAdd(cnt, 0u) < target) { __nanosleep(64); }
    }
    __syncthreads();
}
__device__ __forceinline__ void arrive(unsigned* cnt) {
    __threadfence();
    __syncthreads();
    if (threadIdx.x == 0) atomicAdd(cnt, 1u);
}
__device__ __forceinline__ float wredsum(float v) {
#pragma unroll
    for (int o = 16; o; o >>= 1) v += __shfl_xor_sync(0xffffffffu, v, o);
    return v;
}

// ---------------- MMA bodies ----------------
// precompute 64x64: warps 4(M)x2(N), warp tile 16x32
__device__ __forceinline__ void mma64q(const unsigned* As, const unsigned* Bs,
                                       float acc[4][4], int wm, int wn, int lane) {
#pragma unroll
    for (int ks = 0; ks < 8; ks++) {
        uint4 a = *(const uint4*)&As[((wm * 8 + ks) * 32 + lane) * 4];
        uint4 b0 = *(const uint4*)&Bs[(((wn * 2 + 0) * 8 + ks) * 32 + lane) * 4];
        uint4 b1 = *(const uint4*)&Bs[(((wn * 2 + 1) * 8 + ks) * 32 + lane) * 4];
        MMA(acc[0], a.x, a.y, a.z, a.w, b0.x, b0.y);
        MMA(acc[1], a.x, a.y, a.z, a.w, b0.z, b0.w);
        MMA(acc[2], a.x, a.y, a.z, a.w, b1.x, b1.y);
        MMA(acc[3], a.x, a.y, a.z, a.w, b1.z, b1.w);
    }
}
// team-A 64x16: warps 4(M)x2(N), warp tile 16x8
__device__ __forceinline__ void mma16q(const unsigned* As, const unsigned* Bs,
                                       float acc[4], int wm, int wn, int lane) {
#pragma unroll
    for (int ks = 0; ks < 8; ks++) {
        uint4 a = *(const uint4*)&As[((wm * 8 + ks) * 32 + lane) * 4];
        uint4 b = *(const uint4*)&Bs[(ks * 32 + lane) * 4];
        unsigned b0 = wn ? b.z : b.x;
        unsigned b1 = wn ? b.w : b.y;
        MMA(acc, a.x, a.y, a.z, a.w, b0, b1);
    }
}
// team-B 64x128 with 2-way k-split: warps 2(M)x2(N64)x2(K), warp tile 32x64
__device__ __forceinline__ void mma128k(const unsigned* As, const unsigned* Bs,
                                        float acc[2][8][4], int wm, int wn2, int kw,
                                        int lane) {
    const unsigned* Bt = Bs + wn2 * 4096;
#pragma unroll
    for (int kk = 0; kk < 4; kk++) {
        int ks = kw * 4 + kk;
        uint4 a0 = *(const uint4*)&As[(((wm * 2 + 0) * 8 + ks) * 32 + lane) * 4];
        uint4 a1 = *(const uint4*)&As[(((wm * 2 + 1) * 8 + ks) * 32 + lane) * 4];
#pragma unroll
        for (int nb = 0; nb < 4; nb++) {
            uint4 b = *(const uint4*)&Bt[((nb * 8 + ks) * 32 + lane) * 4];
            MMA(acc[0][nb * 2 + 0], a0.x, a0.y, a0.z, a0.w, b.x, b.y);
            MMA(acc[0][nb * 2 + 1], a0.x, a0.y, a0.z, a0.w, b.z, b.w);
            MMA(acc[1][nb * 2 + 0], a1.x, a1.y, a1.z, a1.w, b.x, b.y);
            MMA(acc[1][nb * 2 + 1], a1.x, a1.y, a1.z, a1.w, b.z, b.w);
        }
    }
}

__device__ __forceinline__ const unsigned* pcA(int g, int t, int par, int kc) {
    if (kc < 4)  return g_ccq + ((size_t)g * 4 + kc) * 4096;
    if (kc < 8)  return g_mq + (((size_t)g * Tn + t) * 4 + (kc - 4)) * 4096;
    return g_hq + (((size_t)par * 4 + g) * 8 + (kc - 8)) * 4096;
}
__device__ __forceinline__ int pc_ord(int i) {
    return (i < 8) ? (8 + i) : ((i < 12) ? (i - 4) : (i - 12));
}

__global__ void __launch_bounds__(NT, 1) rits_kernel(
    const float* __restrict__ values, const float* __restrict__ masks,
    const float* __restrict__ deltas,
    const float* __restrict__ W_td_h, const float* __restrict__ b_td_h,
    const float* __restrict__ W_td_x, const float* __restrict__ b_td_x,
    const float* __restrict__ W_hist, const float* __restrict__ b_hist,
    const float* __restrict__ W_feat, const float* __restrict__ b_feat,
    const float* __restrict__ W_comb, const float* __restrict__ b_comb,
    const float* __restrict__ W_ih, const float* __restrict__ W_hh,
    const float* __restrict__ b_ih, const float* __restrict__ b_hh,
    float* __restrict__ out)
{
    extern __shared__ unsigned SHu[];
    float* RED = (float*)(SHu + NSTG * STW);
    unsigned sbase = (unsigned)__cvta_generic_to_shared(SHu);

    const int tid = threadIdx.x;
    const int cta = blockIdx.x;
    const int wid = tid >> 5;
    const int lane = tid & 31;
    const int gid = lane >> 2;
    const int tg = lane & 3;
    const int wm = wid & 3, wn = wid >> 2;          // precompute / team-A grid
    const int wmB = wid & 1;                        // team-B: 32-row half
    const int wn2 = (wid >> 1) & 1;                 // team-B: 64-n tile
    const int kw = wid >> 2;                        // team-B: k half

    const int g = cta >> 5;
    const int cg = cta & 31;
    const int b0 = g * 64;
    const int gtid = cta * NT + tid;

    unsigned sense = *((volatile unsigned*)&g_sense);

    // =================== init (proven, unchanged) ===================
    for (int i = gtid; i < Bn * Hn; i += NTH) g_cst[i] = 0.0f;
    for (int i = gtid; i < 2 * 4 * 8 * 4096; i += NTH) g_hq[i] = 0u;

    {
        float* DIAG = (float*)SHu;
        float* BTDX = (float*)SHu + 256;
        if (tid < 256) {
            DIAG[tid] = W_td_x[tid * Fn + tid];
            BTDX[tid] = b_td_x[tid];
        }
        __syncthreads();
        for (int task = gtid; task < 409600; task += NTH) {
            int u = task >> 10;
            int rem = task & 1023;
            int kc = rem >> 8;
            int w = rem & 255;
            int ko = w & 7, rp = w >> 3;
            int rblk = rp >> 3, r0 = rp & 7;
            int bt_lo = u * 64 + rblk * 16 + r0;
            int f0 = kc * 64 + ko * 8;
            float dlo[8], dhi[8], mlo[8], mhi[8], glo[8], ghi[8];
            load8(&deltas[(size_t)bt_lo * Fn + f0], dlo);
            load8(&deltas[(size_t)(bt_lo + 8) * Fn + f0], dhi);
            load8(&masks[(size_t)bt_lo * Fn + f0], mlo);
            load8(&masks[(size_t)(bt_lo + 8) * Fn + f0], mhi);
#pragma unroll
            for (int q = 0; q < 8; q++) {
                float dg = DIAG[f0 + q], bb = BTDX[f0 + q];
                glo[q] = expf(-fmaxf(fmaf(dlo[q], dg, bb), 0.f));
                ghi[q] = expf(-fmaxf(fmaf(dhi[q], dg, bb), 0.f));
            }
            storeA16(g_dtq + ((size_t)u * 4 + kc) * 4096, rblk, r0, ko, dlo, dhi);
            storeA16(g_gxmq + ((size_t)u * 8 + kc) * 4096, rblk, r0, ko, glo, ghi);
            storeA16(g_gxmq + ((size_t)u * 8 + 4 + kc) * 4096, rblk, r0, ko, mlo, mhi);
        }
        for (int task = gtid; task < 409600; task += NTH) {
            int gt = task >> 10;
            int rem = task & 1023;
            int kc = rem >> 8;
            int w = rem & 255;
            int ko = w & 7, rp = w >> 3;
            int rblk = rp >> 3, r0 = rp & 7;
            int g2 = gt / Tn, t = gt - g2 * Tn;
            int blo = g2 * 64 + rblk * 16 + r0;
            int f0 = kc * 64 + ko * 8;
            float mlo[8], mhi[8];
            load8(&masks[((size_t)blo * Tn + t) * Fn + f0], mlo);
            load8(&masks[((size_t)(blo + 8) * Tn + t) * Fn + f0], mhi);
            storeA16(g_mq + (((size_t)g2 * Tn + t) * 4 + kc) * 4096, rblk, r0, ko, mlo, mhi);
        }
        __syncthreads();
    }

    for (int task = gtid; task < 8192; task += NTH) {
        int tile = task >> 8;
        int w = task & 255, ko = w & 7, np = w >> 3;
        int nblk = np >> 3, n0 = np & 7;
        int nt = tile >> 2, kt = tile & 3;
        int n_lo = nt * 64 + nblk * 16 + n0;
        int kg = kt * 64 + ko * 8;
        float lo[8], hi[8];
        load8(&W_td_h[(size_t)n_lo * 256 + kg], lo);
        load8(&W_td_h[(size_t)(n_lo + 8) * 256 + kg], hi);
        storeB16(g_Wtdhq + (size_t)tile * 4096, nblk, n0, ko, lo, hi);
    }
    for (int task = gtid; task < 8192; task += NTH) {
        int tile = task >> 8;
        int w = task & 255, ko = w & 7, np = w >> 3;
        int nblk = np >> 3, n0 = np & 7;
        int nt = tile >> 3, kt = tile & 7;
        int n_lo = nt * 64 + nblk * 16 + n0;
        int kg = kt * 64 + ko * 8;
        float lo[8], hi[8];
        load8(&W_comb[(size_t)n_lo * 512 + kg], lo);
        load8(&W_comb[(size_t)(n_lo + 8) * 512 + kg], hi);
        storeB16(g_Wcombq + (size_t)tile * 4096, nblk, n0, ko, lo, hi);
    }
    for (int task = gtid; task < 8192; task += NTH) {
        int tile = task >> 6;
        int w = task & 63, ko = w & 7, np = w >> 3;
        int nt = tile >> 3, kt = tile & 7;
        int n_lo = nt * 16 + np;
        int kg = kt * 64 + ko * 8;
        float lo[8], hi[8];
        load8(&W_hist[(size_t)n_lo * 512 + kg], lo);
        load8(&W_hist[(size_t)(n_lo + 8) * 512 + kg], hi);
        storeB16(g_Whistq + (size_t)tile * 1024, 0, np, ko, lo, hi);
    }
    for (int task = gtid; task < 4096; task += NTH) {
        int tile = task >> 6;
        int w = task & 63, ko = w & 7, np = w >> 3;
        int nt = tile >> 2, kt = tile & 3;
        int n_lo = nt * 16 + np;
        int kg = kt * 64 + ko * 8;
        float lo[8], hi[8];
        load8(&W_feat[(size_t)n_lo * 256 + kg], lo);
        load8(&W_feat[(size_t)(n_lo + 8) * 256 + kg], hi);
#pragma unroll
        for (int q = 0; q < 8; q++) {
            if (n_lo == kg + q) lo[q] = 0.0f;
            if (n_lo + 8 == kg + q) hi[q] = 0.0f;
        }
        storeB16(g_Wfeatq + (size_t)tile * 1024, 0, np, ko, lo, hi);
    }
    for (int task = gtid; task < 131072; task += NTH) {
        int tile = task >> 8;
        int w = task & 255, ko = w & 7, np = w >> 3;
        int nblk = np >> 3, n0 = np & 7;
        int nt = tile >> 4, kt = tile & 15;
        int n_lo = nt * 64 + nblk * 16 + n0;
        int kg = kt * 64 + ko * 8;
        int j = n_lo >> 2, gate = n_lo & 3;
        const float* src_lo;
        const float* src_hi;
        if (kg < 512) {
            src_lo = &W_ih[(size_t)(gate * Hn + j) * 512 + kg];
            src_hi = &W_ih[(size_t)(gate * Hn + j + 2) * 512 + kg];
        } else {
            src_lo = &W_hh[(size_t)(gate * Hn + j) * 512 + (kg - 512)];
            src_hi = &W_hh[(size_t)(gate * Hn + j + 2) * 512 + (kg - 512)];
        }
        float lo[8], hi[8];
        load8(src_lo, lo);
        load8(src_hi, hi);
        storeB16(g_Wgq + (size_t)tile * 4096, nblk, n0, ko, lo, hi);
    }
    for (int i = gtid; i < 4 * Hn; i += NTH) {
        int j = i >> 2, gate = i & 3;
        g_bg[i] = b_ih[gate * Hn + j] + b_hh[gate * Hn + j];
    }
    gsync(sense);

    // =================== precompute gamma_h + alpha (unchanged) ===================
    for (int tt = cta; tt < 4800; tt += NB) {
        float acc[4][4];
#pragma unroll
        for (int nf = 0; nf < 4; nf++)
#pragma unroll
            for (int e = 0; e < 4; e++) acc[nf][e] = 0.0f;

        const bool isg = (tt < 3200);
        const int u = isg ? tt : tt - 3200;
        const int ut = isg ? (u >> 3) : (u >> 2);
        const int nt = isg ? (u & 7) : (u & 3);
        const int m0 = ut * 64, n0 = nt * 64;
        const int NI = isg ? 4 : 8;
        const unsigned* Asrc = isg ? (g_dtq + (size_t)ut * 4 * 4096)
                                   : (g_gxmq + (size_t)ut * 8 * 4096);
        const unsigned* Bsrc = isg ? (g_Wtdhq + (size_t)nt * 4 * 4096)
                                   : (g_Wcombq + (size_t)nt * 8 * 4096);

        LOADA(Asrc, 0); LOADB4K(Bsrc, 0); CMT;
        LOADA(Asrc + 4096, 1); LOADB4K(Bsrc + 4096, 1); CMT;
        for (int i = 0; i < NI; i++) {
            WAIT1;
            __syncthreads();
            if (i + 2 < NI) {
                LOADA(Asrc + (size_t)(i + 2) * 4096, (i + 2) % 3);
                LOADB4K(Bsrc + (size_t)(i + 2) * 4096, (i + 2) % 3);
            }
            CMT;
            int s = i % 3;
            mma64q(SHu + s * STW, SHu + s * STW + 4096, acc, wm, wn, lane);
        }
        __syncthreads();
#pragma unroll
        for (int nf = 0; nf < 4; nf++) {
#pragma unroll
            for (int ep = 0; ep < 2; ep++) {
                int bt = m0 + wm * 16 + gid + ep * 8;
                int n = n0 + wn * 32 + nf * 8 + 2 * tg;
                float v0 = acc[nf][2 * ep + 0], v1 = acc[nf][2 * ep + 1];
                float2 r;
                if (isg) {
                    r.x = expf(-fmaxf(v0 + b_td_h[n], 0.f));
                    r.y = expf(-fmaxf(v1 + b_td_h[n + 1], 0.f));
                    *(float2*)&g_gamma_h[(size_t)bt * Hn + n] = r;
                } else {
                    r.x = sigmoidf_(v0 + b_comb[n]);
                    r.y = sigmoidf_(v1 + b_comb[n + 1]);
                    *(float2*)&g_alpha[(size_t)bt * Fn + n] = r;
                }
            }
        }
    }
    gsync(sense);

    // ===== team-A: resident weight slices (unchanged) =====
    if (cg < 16) {
        const unsigned* Wh = g_Whistq + (size_t)cg * 8 * 1024;
        const unsigned* Wf = g_Wfeatq + (size_t)cg * 4 * 1024;
#pragma unroll
        for (int j = 0; j < 8; j++) {
            int c = tid + j * 256;
            CPA((unsigned)(RESOFF + c * 4) * 4u, Wh + c * 4);
        }
#pragma unroll
        for (int j = 0; j < 4; j++) {
            int c = tid + j * 256;
            CPA((unsigned)(RESOFF + 8192 + c * 4) * 4u, Wf + c * 4);
        }
        CMT; WAIT0;
        __syncthreads();
    }
    const unsigned* RESH = SHu + RESOFF;
    const unsigned* RESF = SHu + RESOFF + 8192;

    // =================== recurrence: team-split dataflow ===================
    for (int t = 0; t < Tn; t++) {
        const int par = t & 1, nxt = (t + 1) & 1;

        if (cg < 16) {
            // ===== team A (unchanged from R16) =====
            const int n0 = cg * 16;
            float xh_r[4], x_r[4], m_r[4];
            {   // P_a
                const unsigned* Ah = g_hq + (((size_t)par * 4 + g) * 8) * 4096;
#pragma unroll
                for (int hh = 0; hh < 2; hh++) {
                    int b = b0 + wm * 16 + gid + hh * 8;
                    int f0 = n0 + wn * 8 + 2 * tg;
                    size_t vi = ((size_t)b * Tn + t) * Fn + f0;
                    float2 xv = *(const float2*)&values[vi];
                    float2 mv = *(const float2*)&masks[vi];
                    x_r[hh * 2 + 0] = xv.x; x_r[hh * 2 + 1] = xv.y;
                    m_r[hh * 2 + 0] = mv.x; m_r[hh * 2 + 1] = mv.y;
                }
                wait_ge(&g_cnt_h[g], 16u * (unsigned)t);
                LOADA2(Ah, 0); CMT;
                LOADA2(Ah + 4096, 1); CMT;
                LOADA2(Ah + 8192, 2); CMT;
                float acc[4] = {0.f, 0.f, 0.f, 0.f};
                for (int i = 0; i < 8; i++) {
                    WAIT2;
                    __syncthreads();
                    if (i + 3 < 8) LOADA2(Ah + (size_t)(i + 3) * 4096, (i + 3) & 3);
                    CMT;
                    mma16q(SHu + (i & 3) * 4096, RESH + i * 1024, acc, wm, wn, lane);
                }
                float ls = 0.0f;
#pragma unroll
                for (int e = 0; e < 4; e++) {
                    int r = wm * 16 + gid + ((e >> 1) << 3);
                    int f = n0 + wn * 8 + 2 * tg + (e & 1);
                    float xh = acc[e] + b_hist[f];
                    float x = x_r[e], m = m_r[e];
                    xh_r[e] = xh;
                    ls += fabsf(xh - x) * m;
                    g_xcq[((size_t)g * 4 + (f >> 6)) * 4096 + o_A(r, f & 63)] =
                        f2tf(m * x + (1.0f - m) * xh);
                }
                arrive(&g_cnt_xh[g]);
                ls = wredsum(ls);
                if (lane == 0) RED[wid] = ls;
                __syncthreads();
                if (tid == 0) {
                    float s = 0.f;
#pragma unroll
                    for (int w = 0; w < 8; w++) s += RED[w];
                    g_l1[t * 64 + g * 16 + cg] = s;
                }
            }
            {   // P_b
                const unsigned* Ax = g_xcq + (size_t)g * 4 * 4096;
                float al_r[4];
#pragma unroll
                for (int hh = 0; hh < 2; hh++) {
                    int b = b0 + wm * 16 + gid + hh * 8;
                    int f0 = n0 + wn * 8 + 2 * tg;
                    size_t vi = ((size_t)b * Tn + t) * Fn + f0;
                    float2 av = *(const float2*)&g_alpha[vi];
                    al_r[hh * 2 + 0] = av.x; al_r[hh * 2 + 1] = av.y;
                }
                __syncthreads();
                wait_ge(&g_cnt_xh[g], 16u * (unsigned)(t + 1));
                LOADA2(Ax, 0); CMT;
                LOADA2(Ax + 4096, 1); CMT;
                LOADA2(Ax + 8192, 2); CMT;
                float acc[4] = {0.f, 0.f, 0.f, 0.f};
                for (int i = 0; i < 4; i++) {
                    WAIT2;
                    __syncthreads();
                    if (i + 3 < 4) LOADA2(Ax + (size_t)(i + 3) * 4096, (i + 3) & 3);
                    CMT;
                    mma16q(SHu + (i & 3) * 4096, RESF + i * 1024, acc, wm, wn, lane);
                }
                float l2s = 0.f, l3s = 0.f, dns = 0.f;
#pragma unroll
                for (int e = 0; e < 4; e++) {
                    int r = wm * 16 + gid + ((e >> 1) << 3);
                    int b = b0 + r;
                    int f = n0 + wn * 8 + 2 * tg + (e & 1);
                    size_t vi = ((size_t)b * Tn + t) * Fn + f;
                    float z = fmaxf(acc[e] + b_feat[f], 0.0f);
                    float al = al_r[e];
                    float x = x_r[e], m = m_r[e];
                    float ch = al * z + (1.0f - al) * xh_r[e];
                    float cc = m * x + (1.0f - m) * ch;
                    out[vi] = cc;
                    g_ccq[((size_t)g * 4 + (f >> 6)) * 4096 + o_A(r, f & 63)] = f2tf(cc);
                    l2s += fabsf(z - x) * m;
                    l3s += fabsf(ch - x) * m;
                    dns += m;
                }
                arrive(&g_cnt_cc[g]);
                l2s = wredsum(l2s); l3s = wredsum(l3s); dns = wredsum(dns);
                if (lane == 0) { RED[wid] = l2s; RED[8 + wid] = l3s; RED[16 + wid] = dns; }
                __syncthreads();
                if (tid == 0) {
                    float s2 = 0.f, s3 = 0.f, sd = 0.f;
#pragma unroll
                    for (int w = 0; w < 8; w++) { s2 += RED[w]; s3 += RED[8 + w]; sd += RED[16 + w]; }
                    int slot = t * 64 + g * 16 + cg;
                    g_l2[slot] = s2; g_l3[slot] = s3; g_den[slot] = sd;
                }
            }
        } else {
            // ===== team B: P_c (64x128, K=1024, 32x64 warp tiles, 2-way k-split) =====
            const int cg16 = cg - 16;
            const int j0 = cg16 * 32;
            const unsigned* Bt0 = g_Wgq + ((size_t)(cg16 * 2 + 0) * 16) * 4096;
            const unsigned* Bt1 = g_Wgq + ((size_t)(cg16 * 2 + 1) * 16) * 4096;
            LOADBPC(Bt0 + (size_t)pc_ord(0) * 4096, Bt1 + (size_t)pc_ord(0) * 4096, 0);
            LOADBPC(Bt0 + (size_t)pc_ord(1) * 4096, Bt1 + (size_t)pc_ord(1) * 4096, 1);
            CMT;
            float cst_r[8], gam_r[8];
#pragma unroll
            for (int q = 0; q < 8; q++) {
                int idx = tid + q * 256;
                int r = idx >> 5, jl = idx & 31;
                int b = b0 + r;
                int j = j0 + jl;
                cst_r[q] = g_cst[b * Hn + j];
                gam_r[q] = (t + 1 < Tn)
                         ? g_gamma_h[((size_t)b * Tn + t + 1) * Hn + j] : 0.0f;
            }
            wait_ge(&g_cnt_h[g], 16u * (unsigned)t);
            LOADA(pcA(g, t, par, pc_ord(0)), 0); CMT;
            LOADA(pcA(g, t, par, pc_ord(1)), 1); CMT;
            float acc[2][8][4];
#pragma unroll
            for (int mi = 0; mi < 2; mi++)
#pragma unroll
                for (int nf = 0; nf < 8; nf++)
#pragma unroll
                    for (int e = 0; e < 4; e++) acc[mi][nf][e] = 0.0f;
            for (int i = 0; i < 16; i++) {
                WAIT1;
                __syncthreads();
                if (i == 10) wait_ge(&g_cnt_cc[g], 16u * (unsigned)(t + 1));
                if (i + 2 < 16) {
                    int kc = pc_ord(i + 2);
                    LOADA(pcA(g, t, par, kc), (i + 2) % 3);
                    LOADBPC(Bt0 + (size_t)kc * 4096, Bt1 + (size_t)kc * 4096, (i + 2) % 3);
                }
                CMT;
                int s = i % 3;
                mma128k(SHu + s * STW, SHu + s * STW + 4096, acc, wmB, wn2, kw, lane);
            }
            // k-split reduce through dead stage-1 region
            float* PRT = (float*)(SHu + STW);
            __syncthreads();
            if (kw == 1) {
                float* p = PRT + (wmB * 2 + wn2) * 2048 + lane * 64;
#pragma unroll
                for (int mi = 0; mi < 2; mi++)
#pragma unroll
                    for (int nf = 0; nf < 8; nf++)
#pragma unroll
                        for (int e = 0; e < 4; e++)
                            p[mi * 32 + nf * 4 + e] = acc[mi][nf][e];
            }
            __syncthreads();
            float* EP = (float*)SHu;
            if (kw == 0) {
                const float* p = PRT + (wmB * 2 + wn2) * 2048 + lane * 64;
#pragma unroll
                for (int mi = 0; mi < 2; mi++)
#pragma unroll
                    for (int nf = 0; nf < 8; nf++)
#pragma unroll
                        for (int e = 0; e < 4; e++) {
                            float v = acc[mi][nf][e] + p[mi * 32 + nf * 4 + e];
                            int r = wmB * 32 + mi * 16 + gid + ((e >> 1) << 3);
                            int c = wn2 * 64 + nf * 8 + 2 * tg + (e & 1);
                            EP[r * EPIT + c] = v;
                        }
            }
            __syncthreads();
#pragma unroll
            for (int q = 0; q < 8; q++) {
                int idx = tid + q * 256;
                int r = idx >> 5, jl = idx & 31;
                int b = b0 + r;
                int j = j0 + jl;
                float ia = EP[r * EPIT + jl * 4 + 0] + g_bg[j * 4 + 0];
                float fa = EP[r * EPIT + jl * 4 + 1] + g_bg[j * 4 + 1];
                float ga = EP[r * EPIT + jl * 4 + 2] + g_bg[j * 4 + 2];
                float oa = EP[r * EPIT + jl * 4 + 3] + g_bg[j * 4 + 3];
                int ci = b * Hn + j;
                float cn = sigmoidf_(fa) * cst_r[q] + sigmoidf_(ia) * tanhf(ga);
                float hn = sigmoidf_(oa) * tanhf(cn);
                g_cst[ci] = cn;
                if (t + 1 < Tn) {
                    g_hq[(((size_t)nxt * 4 + g) * 8 + (j >> 6)) * 4096 + o_A(r, j & 63)] =
                        f2tf(hn * gam_r[q]);
                } else {
                    out[BTF + ci] = hn;
                }
            }
            arrive(&g_cnt_h[g]);
        }
    }

    gsync(sense);

    // =================== final loss reduction + counter reset ===================
    if (cta == 0) {
        float v = 0.0f;
        if (tid < Tn) {
            float den = 1e-9f, n1 = 0.f, n2 = 0.f, n3 = 0.f;
            for (int c2 = 0; c2 < 64; c2++) {
                den += g_den[tid * 64 + c2];
                n1 += g_l1[tid * 64 + c2];
                n2 += g_l2[tid * 64 + c2];
                n3 += g_l3[tid * 64 + c2];
            }
            v = (n1 + n2 + n3) / den;
        }
        __syncthreads();
        RED[tid] = v;
        __syncthreads();
#pragma unroll
        for (int s = 128; s > 0; s >>= 1) {
            if (tid < s) RED[tid] += RED[tid + s];
            __syncthreads();
        }
        if (tid == 0) {
            out[BTF + Bn * Hn] = RED[0] / (3.0f * Tn);
#pragma unroll
            for (int i = 0; i < 4; i++) { g_cnt_h[i] = 0u; g_cnt_xh[i] = 0u; g_cnt_cc[i] = 0u; }
            __threadfence();
        }
    }
}

extern "C" void kernel_launch(void* const* d_in, const int* in_sizes, int n_in,
                              void* d_out, int out_size) {
    (void)in_sizes; (void)n_in; (void)out_size;
    static int configured = 0;
    if (!configured) {
        cudaFuncSetAttribute(rits_kernel, cudaFuncAttributeMaxDynamicSharedMemorySize,
                             SMEM_BYTES);
        configured = 1;
    }
    rits_kernel<<<NB, NT, SMEM_BYTES>>>(
        (const float*)d_in[0],  (const float*)d_in[1],  (const float*)d_in[2],
        (const float*)d_in[3],  (const float*)d_in[4],  (const float*)d_in[5],
        (const float*)d_in[6],  (const float*)d_in[7],  (const float*)d_in[8],
        (const float*)d_in[9],  (const float*)d_in[10], (const float*)d_in[11],
        (const float*)d_in[12], (const float*)d_in[13], (const float*)d_in[14],
        (const float*)d_in[15], (const float*)d_in[16],
        (float*)d_out);
}